// round 10
// baseline (speedup 1.0000x reference)
#include <cuda_runtime.h>
#include <math.h>

#define Bq 16
#define Sq 2048
#define Dq 128
#define Hq 8
#define BH 128
#define MCH 16                 // mem chunk (timesteps)
#define SCH 64                 // scan chunk
#define NCH (Sq/SCH)
#define CUT 1e-4f

// dynamic smem float layout
#define OFF_WK 0
#define OFF_WV 16384
#define OFF_XB 32768           // 64 rows * stride 132 = 8448 (scan-chunk x cache)
#define OFF_K  41216           // 16 * 132 = 2112 (rows c-scaled)
#define OFF_V  43328           // 2112
#define OFF_C  45440           // 2048
#define SMEM_FLOATS 47488

typedef unsigned long long u64;

__device__ __forceinline__ u64 pack2(float lo, float hi) {
    u64 r; asm("mov.b64 %0, {%1, %2};" : "=l"(r) : "f"(lo), "f"(hi)); return r;
}
__device__ __forceinline__ void unpack2(u64 v, float& lo, float& hi) {
    asm("mov.b64 {%0, %1}, %2;" : "=f"(lo), "=f"(hi) : "l"(v));
}
__device__ __forceinline__ u64 fma2(u64 a, u64 b, u64 c) {
    u64 d; asm("fma.rn.f32x2 %0, %1, %2, %3;" : "=l"(d) : "l"(a), "l"(b), "l"(c));
    return d;
}

// ---------------------------------------------------------------------------
// One block per (b,h).
// Phase 0: cp.async prefetch of Wk_h/Wv_h into smem (completes after phase 1).
// Phase 1: backward scan w/ early exit; while computing f, the chunk's x rows
//          are cached in smem (xbig) so phase 2 needs no global restaging.
// Phase 2: chunked (16-step) K/V projection + rank-16 outer products in packed
//          f32x2 FFMA2; acc += P*M0 (skipped when P==0); single store.
// ---------------------------------------------------------------------------
__global__ __launch_bounds__(512) void fused_kernel(
    const float* __restrict__ x, const float* __restrict__ M0,
    const float* __restrict__ router, const int* __restrict__ memid,
    const float* __restrict__ Wk, const float* __restrict__ bk,
    const float* __restrict__ Wv, const float* __restrict__ bv,
    const float* __restrict__ Wf, const float* __restrict__ bf,
    float* __restrict__ out, int nm)
{
    extern __shared__ float sm[];
    float* Wk_s = sm + OFF_WK;
    float* Wv_s = sm + OFF_WV;
    float* xbig = sm + OFF_XB;    // [row][d], stride 132 (64 rows)
    float* k_s  = sm + OFF_K;     // [row][d], stride 132 (rows c-scaled)
    float* v_s  = sm + OFF_V;
    float* c_s  = sm + OFF_C;     // indexed by global t

    __shared__ float wfh[Dq];
    __shared__ float f_s[SCH], csp[SCH];
    __shared__ float s_sp, s_newsp;
    __shared__ int   s_t0i;

    int tid = threadIdx.x, bh = blockIdx.x, b = bh >> 3, h = bh & 7;

    // phase 0: async weight prefetch (overlaps with phase 1)
    for (int idx = tid; idx < Dq * 32; idx += 512) {
        int d = idx >> 5, q = idx & 31;
        unsigned int dk = (unsigned int)__cvta_generic_to_shared(&Wk_s[d * Dq + q * 4]);
        unsigned int dv = (unsigned int)__cvta_generic_to_shared(&Wv_s[d * Dq + q * 4]);
        const float* sk = &Wk[(size_t)d * (Dq * Hq) + h * Dq + q * 4];
        const float* sv = &Wv[(size_t)d * (Dq * Hq) + h * Dq + q * 4];
        asm volatile("cp.async.ca.shared.global [%0], [%1], 16;" :: "r"(dk), "l"(sk));
        asm volatile("cp.async.ca.shared.global [%0], [%1], 16;" :: "r"(dv), "l"(sv));
    }
    asm volatile("cp.async.commit_group;" ::: "memory");

    for (int d = tid; d < Dq; d += 512) wfh[d] = Wf[d * Hq + h];
    float bfh = bf[h];
    int mid = *memid;
    if (tid == 0) { s_sp = 1.0f; s_t0i = SCH; }
    __syncthreads();

    // ---- phase 1: backward scan with early exit ----
    int t0_exact = 0;
    int xb_t0 = (NCH - 1) * SCH;   // global t of xbig[0] after the loop
    float P = 0.0f;

    for (int ci = NCH - 1; ci >= 0; ci--) {
        int tc = ci * SCH;

        // independent router load issued early (tid<64)
        float wrt = 0.f;
        if (tid < SCH)
            wrt = router[((size_t)b * Sq + tc + tid) * nm + mid];

        // f for 64 timesteps: 8 threads per t, direct LDG + shfl reduce;
        // side effect: cache x rows into xbig.
        {
            int t8 = tid >> 3, sub = tid & 7;
            const float* xp = &x[((size_t)b * Sq + tc + t8) * Dq + sub * 16];
            float a = 0.f;
            #pragma unroll
            for (int j = 0; j < 4; j++) {
                float4 xv = *(const float4*)&xp[j * 4];
                const float* wp = &wfh[sub * 16 + j * 4];
                a += xv.x * wp[0] + xv.y * wp[1] + xv.z * wp[2] + xv.w * wp[3];
                *(float4*)&xbig[t8 * 132 + sub * 16 + j * 4] = xv;
            }
            a += __shfl_xor_sync(0xffffffffu, a, 1);
            a += __shfl_xor_sync(0xffffffffu, a, 2);
            a += __shfl_xor_sync(0xffffffffu, a, 4);
            if (sub == 0) f_s[t8] = 1.0f / (1.0f + __expf(-(a + bfh)));
        }
        __syncthreads();

        // warp 0: suffix-product scan over the 64 f values (2 per lane)
        if (tid < 32) {
            float f0 = f_s[2 * tid], f1 = f_s[2 * tid + 1];
            float p = f0 * f1;
            float incl = p;                       // prod_{j>=lane} p_j
            #pragma unroll
            for (int off = 1; off < 32; off <<= 1) {
                float v = __shfl_down_sync(0xffffffffu, incl, off);
                if (tid + off < 32) incl *= v;
            }
            float excl = __shfl_down_sync(0xffffffffu, incl, 1);
            if (tid == 31) excl = 1.0f;           // prod_{j>lane} p_j
            float sp0 = s_sp;
            float c1 = sp0 * excl;                // suffix after t = 2*lane+1
            float c0 = c1 * f1;                   // suffix after t = 2*lane
            csp[2 * tid]     = c0;
            csp[2 * tid + 1] = c1;
            if (tid == 0) s_newsp = sp0 * incl;
        }
        __syncthreads();

        if (tid < SCH) {
            c_s[tc + tid] = wrt * csp[tid];
            if (csp[tid] >= CUT) atomicMin(&s_t0i, tid);
        }
        __syncthreads();

        float nsp = s_newsp;
        if (nsp < CUT) { t0_exact = tc + s_t0i; xb_t0 = tc; break; }
        if (tid == 0) { s_sp = nsp; s_t0i = SCH; }
        if (ci == 0) { P = nsp; t0_exact = 0; xb_t0 = 0; }
        __syncthreads();
    }

    // weights must be resident before phase 2
    asm volatile("cp.async.wait_group 0;" ::: "memory");
    __syncthreads();

    // ---- phase 2: chunked projection + outer products (f32x2) ----
    int dg = tid >> 4, eg = tid & 15, d0 = dg * 4, e0 = eg * 8;
    u64 acc2[4][4];
    u64 z = pack2(0.f, 0.f);
    #pragma unroll
    for (int r = 0; r < 4; r++)
        #pragma unroll
        for (int q = 0; q < 4; q++) acc2[r][q] = z;

    int half = tid >> 8, id2 = tid & 255;
    int rg = id2 & 15;        // projection row (timestep within chunk)
    int cg = id2 >> 4;        // projection cols cg*8..+7
    float* op = half ? v_s : k_s;
    const float* Ws = half ? Wv_s : Wk_s;
    float bias[8];
    {
        const float* bsrc = half ? bv : bk;
        #pragma unroll
        for (int j = 0; j < 8; j++) bias[j] = bsrc[h * Dq + cg * 8 + j];
    }

    int t_start = t0_exact & ~(MCH - 1);
    for (int tc = t_start; tc < Sq; tc += MCH) {
        const float* xbase;
        if (tc >= xb_t0 && tc + MCH <= xb_t0 + SCH) {
            // chunk already cached in xbig by phase 1 (common case)
            xbase = &xbig[(tc - xb_t0) * 132];
        } else {
            // rare: window crosses scan chunks -> stage via LDG into k_s..?? no:
            // stage into the first 16 rows of xbig's tail region is unsafe if it
            // overlaps a cached chunk we still need; use a dedicated restage of
            // xbig rows [48..64) only when outside: simplest is re-LDG into
            // xbig[(tc % SCH)] rows -- they are not needed again afterwards.
            __syncthreads();
            int row = tid >> 5, lane = tid & 31;
            float* dst = &xbig[((tc % SCH) + row) * 132];
            float4 xv = *(const float4*)&x[((size_t)b * Sq + tc + row) * Dq + lane * 4];
            *(float4*)&dst[lane * 4] = xv;
            xbase = &xbig[(tc % SCH) * 132];
            __syncthreads();
        }

        // projection: 1 row x 8 cols as 4 packed f32x2 pairs
        u64 pa2[4] = {z, z, z, z};
        #pragma unroll 4
        for (int d4 = 0; d4 < Dq / 4; d4++) {
            float4 xa = *(const float4*)&xbase[rg * 132 + d4 * 4];
            float xr[4] = {xa.x, xa.y, xa.z, xa.w};
            #pragma unroll
            for (int u = 0; u < 4; u++) {
                int d = d4 * 4 + u;
                ulonglong2 wA = *(const ulonglong2*)&Ws[d * Dq + cg * 8];
                ulonglong2 wB = *(const ulonglong2*)&Ws[d * Dq + cg * 8 + 4];
                u64 xb = pack2(xr[u], xr[u]);
                pa2[0] = fma2(xb, wA.x, pa2[0]);
                pa2[1] = fma2(xb, wA.y, pa2[1]);
                pa2[2] = fma2(xb, wB.x, pa2[2]);
                pa2[3] = fma2(xb, wB.y, pa2[3]);
            }
        }
        __syncthreads();   // prev outer-product reads of k_s/v_s complete
        {
            float scale = half ? 1.0f : c_s[tc + rg];   // fold c_t into k rows
            float o[8];
            #pragma unroll
            for (int q = 0; q < 4; q++) unpack2(pa2[q], o[2 * q], o[2 * q + 1]);
            #pragma unroll
            for (int j = 0; j < 8; j++) o[j] = (o[j] + bias[j]) * scale;
            *(float4*)&op[rg * 132 + cg * 8]     = make_float4(o[0], o[1], o[2], o[3]);
            *(float4*)&op[rg * 132 + cg * 8 + 4] = make_float4(o[4], o[5], o[6], o[7]);
        }
        __syncthreads();

        // rank-16 outer-product update: 4x8 tile as 4x4 packed pairs
        #pragma unroll 4
        for (int i = 0; i < MCH; i++) {
            float4 k0 = *(const float4*)&k_s[i * 132 + d0];
            ulonglong2 va = *(const ulonglong2*)&v_s[i * 132 + e0];
            ulonglong2 vb = *(const ulonglong2*)&v_s[i * 132 + e0 + 4];
            u64 kp[4] = {pack2(k0.x, k0.x), pack2(k0.y, k0.y),
                         pack2(k0.z, k0.z), pack2(k0.w, k0.w)};
            #pragma unroll
            for (int r = 0; r < 4; r++) {
                acc2[r][0] = fma2(kp[r], va.x, acc2[r][0]);
                acc2[r][1] = fma2(kp[r], va.y, acc2[r][1]);
                acc2[r][2] = fma2(kp[r], vb.x, acc2[r][2]);
                acc2[r][3] = fma2(kp[r], vb.y, acc2[r][3]);
            }
        }
    }

    // unpack accumulators
    float acc[4][8];
    #pragma unroll
    for (int r = 0; r < 4; r++)
        #pragma unroll
        for (int q = 0; q < 4; q++)
            unpack2(acc2[r][q], acc[r][2 * q], acc[r][2 * q + 1]);

    // add P*M0 only if the full scan completed (else contribution < CUT)
    if (P != 0.0f) {
        #pragma unroll
        for (int r = 0; r < 4; r++) {
            float4 m0 = *(const float4*)&M0[(((size_t)bh * Dq) + d0 + r) * Dq + e0];
            float4 m1 = *(const float4*)&M0[(((size_t)bh * Dq) + d0 + r) * Dq + e0 + 4];
            acc[r][0] += P * m0.x; acc[r][1] += P * m0.y;
            acc[r][2] += P * m0.z; acc[r][3] += P * m0.w;
            acc[r][4] += P * m1.x; acc[r][5] += P * m1.y;
            acc[r][6] += P * m1.z; acc[r][7] += P * m1.w;
        }
    }

    #pragma unroll
    for (int r = 0; r < 4; r++) {
        *(float4*)&out[(((size_t)bh * Dq) + d0 + r) * Dq + e0] =
            make_float4(acc[r][0], acc[r][1], acc[r][2], acc[r][3]);
        *(float4*)&out[(((size_t)bh * Dq) + d0 + r) * Dq + e0 + 4] =
            make_float4(acc[r][4], acc[r][5], acc[r][6], acc[r][7]);
    }
}

// ---------------------------------------------------------------------------
extern "C" void kernel_launch(void* const* d_in, const int* in_sizes, int n_in,
                              void* d_out, int out_size)
{
    const float* x      = (const float*)d_in[0];
    const float* M      = (const float*)d_in[1];
    const float* router = (const float*)d_in[2];
    const int*   memid  = (const int*)d_in[3];
    const float* Wk     = (const float*)d_in[4];
    const float* bk     = (const float*)d_in[5];
    const float* Wv     = (const float*)d_in[6];
    const float* bv     = (const float*)d_in[7];
    const float* Wf     = (const float*)d_in[8];
    const float* bf     = (const float*)d_in[9];

    int nm = in_sizes[2] / (Bq * Sq);   // router last-dim (4)

    static bool attr_done = false;
    if (!attr_done) {
        cudaFuncSetAttribute(fused_kernel,
                             cudaFuncAttributeMaxDynamicSharedMemorySize,
                             SMEM_FLOATS * 4);
        attr_done = true;
    }
    fused_kernel<<<BH, 512, SMEM_FLOATS * 4>>>(
        x, M, router, memid, Wk, bk, Wv, bv, Wf, bf, (float*)d_out, nm);
}

// round 12
// speedup vs baseline: 1.0115x; 1.0115x over previous
#include <cuda_runtime.h>
#include <math.h>

#define Bq 16
#define Sq 2048
#define Dq 128
#define Hq 8
#define BH 128
#define MCH 16                 // mem chunk (timesteps)
#define SCH 64                 // scan chunk
#define NCH (Sq/SCH)
#define CUT 1e-4f

// dynamic smem float layout
#define OFF_WK 0
#define OFF_WV 16384
#define OFF_XB 32768           // 64 rows * stride 132 = 8448 (scan-chunk x cache)
#define OFF_K  41216           // 16 * 132 = 2112 (rows c-scaled)
#define OFF_V  43328           // 2112
#define OFF_C  45440           // 2048
#define SMEM_FLOATS 47488

typedef unsigned long long u64;

__device__ __forceinline__ u64 pack2(float lo, float hi) {
    u64 r; asm("mov.b64 %0, {%1, %2};" : "=l"(r) : "f"(lo), "f"(hi)); return r;
}
__device__ __forceinline__ void unpack2(u64 v, float& lo, float& hi) {
    asm("mov.b64 {%0, %1}, %2;" : "=f"(lo), "=f"(hi) : "l"(v));
}
__device__ __forceinline__ u64 fma2(u64 a, u64 b, u64 c) {
    u64 d; asm("fma.rn.f32x2 %0, %1, %2, %3;" : "=l"(d) : "l"(a), "l"(b), "l"(c));
    return d;
}
__device__ __forceinline__ void cpa16(float* dst, const float* src) {
    unsigned int ds = (unsigned int)__cvta_generic_to_shared(dst);
    asm volatile("cp.async.ca.shared.global [%0], [%1], 16;" :: "r"(ds), "l"(src));
}

// ---------------------------------------------------------------------------
// One block per (b,h).
// Prologue: cp.async group A = last 64 x rows -> xbig; group B = Wk_h/Wv_h.
// Phase 1: backward scan w/ early exit; first chunk reads x from xbig (smem),
//          rare further chunks LDG+cache; c_t = w_t*sp_t in smem.
// Phase 2: exact-window chunks (16 steps) K/V projection + rank-16 outer
//          products in packed f32x2; acc += P*M0 (skipped if P==0); store.
// ---------------------------------------------------------------------------
__global__ __launch_bounds__(512) void fused_kernel(
    const float* __restrict__ x, const float* __restrict__ M0,
    const float* __restrict__ router, const int* __restrict__ memid,
    const float* __restrict__ Wk, const float* __restrict__ bk,
    const float* __restrict__ Wv, const float* __restrict__ bv,
    const float* __restrict__ Wf, const float* __restrict__ bf,
    float* __restrict__ out, int nm)
{
    extern __shared__ float sm[];
    float* Wk_s = sm + OFF_WK;
    float* Wv_s = sm + OFF_WV;
    float* xbig = sm + OFF_XB;    // [row][d], stride 132 (64 rows)
    float* k_s  = sm + OFF_K;     // [row][d], stride 132 (rows c-scaled)
    float* v_s  = sm + OFF_V;
    float* c_s  = sm + OFF_C;     // indexed by global t

    __shared__ float wfh[Dq];
    __shared__ float f_s[SCH], csp[SCH];
    __shared__ float s_sp, s_newsp;
    __shared__ int   s_t0i;

    int tid = threadIdx.x, bh = blockIdx.x, b = bh >> 3, h = bh & 7;

    // group A: prefetch last scan-chunk x rows into xbig
    {
        int tlast = (NCH - 1) * SCH;
        #pragma unroll
        for (int j = 0; j < 4; j++) {
            int idx = tid + 512 * j;
            int row = idx >> 5, q = idx & 31;
            cpa16(&xbig[row * 132 + q * 4],
                  &x[((size_t)b * Sq + tlast + row) * Dq + q * 4]);
        }
    }
    asm volatile("cp.async.commit_group;" ::: "memory");

    // group B: weight prefetch (waited before phase 2)
    for (int idx = tid; idx < Dq * 32; idx += 512) {
        int d = idx >> 5, q = idx & 31;
        cpa16(&Wk_s[d * Dq + q * 4], &Wk[(size_t)d * (Dq * Hq) + h * Dq + q * 4]);
        cpa16(&Wv_s[d * Dq + q * 4], &Wv[(size_t)d * (Dq * Hq) + h * Dq + q * 4]);
    }
    asm volatile("cp.async.commit_group;" ::: "memory");

    // prologue register loads (independent)
    for (int d = tid; d < Dq; d += 512) wfh[d] = Wf[d * Hq + h];
    float bfh = bf[h];
    int mid = *memid;

    int half = tid >> 8, id2 = tid & 255;
    int rg = id2 & 15;        // projection row (timestep within chunk)
    int cg = id2 >> 4;        // projection cols cg*8..+7
    float bias[8];
    {
        const float* bsrc = half ? bv : bk;
        #pragma unroll
        for (int j = 0; j < 8; j++) bias[j] = bsrc[h * Dq + cg * 8 + j];
    }
    if (tid == 0) { s_sp = 1.0f; s_t0i = SCH; }

    // ---- phase 1: backward scan with early exit ----
    int t0_exact = 0;
    int xb_t0 = (NCH - 1) * SCH;   // global t of xbig[0]
    float P = 0.0f;

    for (int ci = NCH - 1; ci >= 0; ci--) {
        int tc = ci * SCH;
        xb_t0 = tc;

        // independent router load issued early (tid<64)
        float wrt = 0.f;
        if (tid < SCH)
            wrt = router[((size_t)b * Sq + tc + tid) * nm + mid];

        if (ci == NCH - 1) {
            // x already inbound via cp.async group A
            asm volatile("cp.async.wait_group 1;" ::: "memory");
            __syncthreads();           // xbig + wfh + s_sp visible
        } else {
            // rare: stage this chunk's x via LDG
            __syncthreads();
            #pragma unroll
            for (int j = 0; j < 4; j++) {
                int idx = tid + 512 * j;
                int row = idx >> 5, q = idx & 31;
                float4 xv = *(const float4*)&x[((size_t)b * Sq + tc + row) * Dq + q * 4];
                *(float4*)&xbig[row * 132 + q * 4] = xv;
            }
            __syncthreads();
        }

        // f for 64 timesteps: 8 threads per t, LDS + shfl reduce
        {
            int t8 = tid >> 3, sub = tid & 7;
            float a = 0.f;
            #pragma unroll
            for (int j = 0; j < 4; j++) {
                float4 xv = *(const float4*)&xbig[t8 * 132 + sub * 16 + j * 4];
                const float* wp = &wfh[sub * 16 + j * 4];
                a += xv.x * wp[0] + xv.y * wp[1] + xv.z * wp[2] + xv.w * wp[3];
            }
            a += __shfl_xor_sync(0xffffffffu, a, 1);
            a += __shfl_xor_sync(0xffffffffu, a, 2);
            a += __shfl_xor_sync(0xffffffffu, a, 4);
            if (sub == 0) f_s[t8] = 1.0f / (1.0f + __expf(-(a + bfh)));
        }
        __syncthreads();

        // warp 0: suffix-product scan over the 64 f values (2 per lane)
        if (tid < 32) {
            float f0 = f_s[2 * tid], f1 = f_s[2 * tid + 1];
            float p = f0 * f1;
            float incl = p;                       // prod_{j>=lane} p_j
            #pragma unroll
            for (int off = 1; off < 32; off <<= 1) {
                float v = __shfl_down_sync(0xffffffffu, incl, off);
                if (tid + off < 32) incl *= v;
            }
            float excl = __shfl_down_sync(0xffffffffu, incl, 1);
            if (tid == 31) excl = 1.0f;           // prod_{j>lane} p_j
            float sp0 = s_sp;
            float c1 = sp0 * excl;                // suffix after t = 2*lane+1
            float c0 = c1 * f1;                   // suffix after t = 2*lane
            csp[2 * tid]     = c0;
            csp[2 * tid + 1] = c1;
            if (tid == 0) s_newsp = sp0 * incl;
        }
        __syncthreads();

        if (tid < SCH) {
            c_s[tc + tid] = wrt * csp[tid];
            if (csp[tid] >= CUT) atomicMin(&s_t0i, tid);
        }
        __syncthreads();

        float nsp = s_newsp;
        if (nsp < CUT) { t0_exact = tc + s_t0i; break; }   // uniform decision
        if (tid == 0) { s_sp = nsp; s_t0i = SCH; }
        if (ci == 0) { P = nsp; t0_exact = 0; }
        __syncthreads();
    }

    // weights must be resident before phase 2
    asm volatile("cp.async.wait_group 0;" ::: "memory");
    __syncthreads();

    // ---- phase 2: exact-window chunks, f32x2 projection + outer product ----
    int dg = tid >> 4, eg = tid & 15, d0 = dg * 4, e0 = eg * 8;
    u64 acc2[4][4];
    u64 z = pack2(0.f, 0.f);
    #pragma unroll
    for (int r = 0; r < 4; r++)
        #pragma unroll
        for (int q = 0; q < 4; q++) acc2[r][q] = z;

    float* op = half ? v_s : k_s;
    const float* Ws = half ? Wv_s : Wk_s;

    // exact window: end-aligned chunks, clamped into the scanned region
    int n = Sq - t0_exact;
    int t_start = Sq - (((n + MCH - 1) >> 4) << 4);
    if (t_start < xb_t0) t_start = xb_t0;

    for (int tc = t_start; tc < Sq; tc += MCH) {
        const float* xbase;
        if (tc >= xb_t0 && tc + MCH <= xb_t0 + SCH) {
            xbase = &xbig[(tc - xb_t0) * 132];    // cached (common case)
        } else {
            // very rare: restage into reusable xbig rows
            __syncthreads();
            int row = tid >> 5, lane = tid & 31;
            float* dst = &xbig[((tc % SCH) + row) * 132];
            float4 xv = *(const float4*)&x[((size_t)b * Sq + tc + row) * Dq + lane * 4];
            *(float4*)&dst[lane * 4] = xv;
            xbase = &xbig[(tc % SCH) * 132];
            __syncthreads();
        }

        // projection: 1 row x 8 cols as 4 packed f32x2 pairs
        u64 pa2[4] = {z, z, z, z};
        #pragma unroll 4
        for (int d4 = 0; d4 < Dq / 4; d4++) {
            float4 xa = *(const float4*)&xbase[rg * 132 + d4 * 4];
            float xr[4] = {xa.x, xa.y, xa.z, xa.w};
            #pragma unroll
            for (int u = 0; u < 4; u++) {
                int d = d4 * 4 + u;
                ulonglong2 wA = *(const ulonglong2*)&Ws[d * Dq + cg * 8];
                ulonglong2 wB = *(const ulonglong2*)&Ws[d * Dq + cg * 8 + 4];
                u64 xb = pack2(xr[u], xr[u]);
                pa2[0] = fma2(xb, wA.x, pa2[0]);
                pa2[1] = fma2(xb, wA.y, pa2[1]);
                pa2[2] = fma2(xb, wB.x, pa2[2]);
                pa2[3] = fma2(xb, wB.y, pa2[3]);
            }
        }
        if (tc != t_start) __syncthreads();   // prior outer reads of k_s/v_s done
        {
            float scale = half ? 1.0f : c_s[tc + rg];   // fold c_t into k rows
            float o[8];
            #pragma unroll
            for (int q = 0; q < 4; q++) unpack2(pa2[q], o[2 * q], o[2 * q + 1]);
            #pragma unroll
            for (int j = 0; j < 8; j++) o[j] = (o[j] + bias[j]) * scale;
            *(float4*)&op[rg * 132 + cg * 8]     = make_float4(o[0], o[1], o[2], o[3]);
            *(float4*)&op[rg * 132 + cg * 8 + 4] = make_float4(o[4], o[5], o[6], o[7]);
        }
        __syncthreads();

        // rank-16 outer-product update: 4x8 tile as 4x4 packed pairs
        #pragma unroll 4
        for (int i = 0; i < MCH; i++) {
            float4 k0 = *(const float4*)&k_s[i * 132 + d0];
            ulonglong2 va = *(const ulonglong2*)&v_s[i * 132 + e0];
            ulonglong2 vb = *(const ulonglong2*)&v_s[i * 132 + e0 + 4];
            u64 kp[4] = {pack2(k0.x, k0.x), pack2(k0.y, k0.y),
                         pack2(k0.z, k0.z), pack2(k0.w, k0.w)};
            #pragma unroll
            for (int r = 0; r < 4; r++) {
                acc2[r][0] = fma2(kp[r], va.x, acc2[r][0]);
                acc2[r][1] = fma2(kp[r], va.y, acc2[r][1]);
                acc2[r][2] = fma2(kp[r], vb.x, acc2[r][2]);
                acc2[r][3] = fma2(kp[r], vb.y, acc2[r][3]);
            }
        }
    }

    // unpack accumulators
    float acc[4][8];
    #pragma unroll
    for (int r = 0; r < 4; r++)
        #pragma unroll
        for (int q = 0; q < 4; q++)
            unpack2(acc2[r][q], acc[r][2 * q], acc[r][2 * q + 1]);

    // add P*M0 only if the full scan completed (else contribution < CUT)
    if (P != 0.0f) {
        #pragma unroll
        for (int r = 0; r < 4; r++) {
            float4 m0 = *(const float4*)&M0[(((size_t)bh * Dq) + d0 + r) * Dq + e0];
            float4 m1 = *(const float4*)&M0[(((size_t)bh * Dq) + d0 + r) * Dq + e0 + 4];
            acc[r][0] += P * m0.x; acc[r][1] += P * m0.y;
            acc[r][2] += P * m0.z; acc[r][3] += P * m0.w;
            acc[r][4] += P * m1.x; acc[r][5] += P * m1.y;
            acc[r][6] += P * m1.z; acc[r][7] += P * m1.w;
        }
    }

    #pragma unroll
    for (int r = 0; r < 4; r++) {
        *(float4*)&out[(((size_t)bh * Dq) + d0 + r) * Dq + e0] =
            make_float4(acc[r][0], acc[r][1], acc[r][2], acc[r][3]);
        *(float4*)&out[(((size_t)bh * Dq) + d0 + r) * Dq + e0 + 4] =
            make_float4(acc[r][4], acc[r][5], acc[r][6], acc[r][7]);
    }
}

// ---------------------------------------------------------------------------
extern "C" void kernel_launch(void* const* d_in, const int* in_sizes, int n_in,
                              void* d_out, int out_size)
{
    const float* x      = (const float*)d_in[0];
    const float* M      = (const float*)d_in[1];
    const float* router = (const float*)d_in[2];
    const int*   memid  = (const int*)d_in[3];
    const float* Wk     = (const float*)d_in[4];
    const float* bk     = (const float*)d_in[5];
    const float* Wv     = (const float*)d_in[6];
    const float* bv     = (const float*)d_in[7];
    const float* Wf     = (const float*)d_in[8];
    const float* bf     = (const float*)d_in[9];

    int nm = in_sizes[2] / (Bq * Sq);   // router last-dim (4)

    static bool attr_done = false;
    if (!attr_done) {
        cudaFuncSetAttribute(fused_kernel,
                             cudaFuncAttributeMaxDynamicSharedMemorySize,
                             SMEM_FLOATS * 4);
        attr_done = true;
    }
    fused_kernel<<<BH, 512, SMEM_FLOATS * 4>>>(
        x, M, router, memid, Wk, bk, Wv, bv, Wf, bf, (float*)d_out, nm);
}

// round 13
// speedup vs baseline: 1.4444x; 1.4281x over previous
#include <cuda_runtime.h>
#include <math.h>

#define Bq 16
#define Sq 2048
#define Dq 128
#define Hq 8
#define BH 128
#define MCH 16                 // unified chunk (scan + mem)
#define NCH (Sq/MCH)           // 128
#define CUT 1e-3f

// dynamic smem float layout
#define OFF_WK 0
#define OFF_WV 16384
#define OFF_XB 32768           // 32 rows * stride 132 (two 16-row buffers)
#define OFF_K  36992           // 16*132
#define OFF_V  39104           // 16*132
#define OFF_C  41216           // 2048
#define SMEM_FLOATS 43264

typedef unsigned long long u64;

__device__ __forceinline__ u64 pack2(float lo, float hi) {
    u64 r; asm("mov.b64 %0, {%1, %2};" : "=l"(r) : "f"(lo), "f"(hi)); return r;
}
__device__ __forceinline__ void unpack2(u64 v, float& lo, float& hi) {
    asm("mov.b64 {%0, %1}, %2;" : "=f"(lo), "=f"(hi) : "l"(v));
}
__device__ __forceinline__ u64 fma2(u64 a, u64 b, u64 c) {
    u64 d; asm("fma.rn.f32x2 %0, %1, %2, %3;" : "=l"(d) : "l"(a), "l"(b), "l"(c));
    return d;
}
__device__ __forceinline__ void cpa16(float* dst, const float* src) {
    unsigned int ds = (unsigned int)__cvta_generic_to_shared(dst);
    asm volatile("cp.async.ca.shared.global [%0], [%1], 16;" :: "r"(ds), "l"(src));
}

// ---------------------------------------------------------------------------
// One block per (b,h). 16-step unified chunks.
// Prologue: cp.async A = last 16 x rows -> xbig buf1; B = Wk_h/Wv_h.
// Phase 1: backward 16-step scan w/ early exit. Warp w computes f for t=w
//          (4 MAC + shfl). Warp 0: 16-lane suffix scan + c_s + ballot t0.
//          x of the last two scanned chunks stays resident (parity buffers).
// Phase 2: end-aligned 16-step chunk(s): K/V projection + rank-16 outer
//          products in packed f32x2; acc += P*M0 (skipped if P==0); store.
// ---------------------------------------------------------------------------
__global__ __launch_bounds__(512) void fused_kernel(
    const float* __restrict__ x, const float* __restrict__ M0,
    const float* __restrict__ router, const int* __restrict__ memid,
    const float* __restrict__ Wk, const float* __restrict__ bk,
    const float* __restrict__ Wv, const float* __restrict__ bv,
    const float* __restrict__ Wf, const float* __restrict__ bf,
    float* __restrict__ out, int nm)
{
    extern __shared__ float sm[];
    float* Wk_s = sm + OFF_WK;
    float* Wv_s = sm + OFF_WV;
    float* xbig = sm + OFF_XB;    // [32][132]; buffer = (chunk&1)*16 rows
    float* k_s  = sm + OFF_K;     // [16][132] (rows c-scaled)
    float* v_s  = sm + OFF_V;
    float* c_s  = sm + OFF_C;     // indexed by global t

    __shared__ float wfh[Dq];
    __shared__ float f_s[MCH];
    __shared__ float s_sp, s_newsp;
    __shared__ int   s_t0i;

    int tid = threadIdx.x, bh = blockIdx.x, b = bh >> 3, h = bh & 7;
    int wid = tid >> 5, lane = tid & 31;

    // group A: prefetch last chunk's x rows into xbig buf1 (chunk 127 & 1 == 1)
    {
        int row = tid >> 5, q = tid & 31;   // 512 threads = 16 rows x 32 quads
        cpa16(&xbig[(16 + row) * 132 + q * 4],
              &x[((size_t)b * Sq + (Sq - MCH) + row) * Dq + q * 4]);
    }
    asm volatile("cp.async.commit_group;" ::: "memory");

    // group B: weight prefetch (waited before phase 2)
    for (int idx = tid; idx < Dq * 32; idx += 512) {
        int d = idx >> 5, q = idx & 31;
        cpa16(&Wk_s[d * Dq + q * 4], &Wk[(size_t)d * (Dq * Hq) + h * Dq + q * 4]);
        cpa16(&Wv_s[d * Dq + q * 4], &Wv[(size_t)d * (Dq * Hq) + h * Dq + q * 4]);
    }
    asm volatile("cp.async.commit_group;" ::: "memory");

    for (int d = tid; d < Dq; d += 512) wfh[d] = Wf[d * Hq + h];
    float bfh = bf[h];
    int mid = *memid;

    int half = tid >> 8, id2 = tid & 255;
    int rg = id2 & 15;        // projection row (timestep within chunk)
    int cg = id2 >> 4;        // projection cols cg*8..+7
    float bias[8];
    {
        const float* bsrc = half ? bv : bk;
        #pragma unroll
        for (int j = 0; j < 8; j++) bias[j] = bsrc[h * Dq + cg * 8 + j];
    }
    if (tid == 0) s_sp = 1.0f;

    // ---- phase 1: backward 16-step scan with early exit ----
    int t0_exact = 0, ci_low = 0;
    float P = 0.0f;

    for (int ci = NCH - 1; ci >= 0; ci--) {
        int tc = ci * MCH;
        int buf = (ci & 1) * 16;

        if (ci == NCH - 1) {
            asm volatile("cp.async.wait_group 1;" ::: "memory");
        } else {
            int row = tid >> 5, q = tid & 31;
            float4 xv = *(const float4*)&x[((size_t)b * Sq + tc + row) * Dq + q * 4];
            *(float4*)&xbig[(buf + row) * 132 + q * 4] = xv;
        }
        __syncthreads();   // x staged + (first iter) wfh/s_sp visible

        // f_t for 16 timesteps: warp w handles t = w
        {
            float4 xv = *(const float4*)&xbig[(buf + wid) * 132 + lane * 4];
            const float* wp = &wfh[lane * 4];
            float a = xv.x * wp[0] + xv.y * wp[1] + xv.z * wp[2] + xv.w * wp[3];
            a += __shfl_xor_sync(0xffffffffu, a, 16);
            a += __shfl_xor_sync(0xffffffffu, a, 8);
            a += __shfl_xor_sync(0xffffffffu, a, 4);
            a += __shfl_xor_sync(0xffffffffu, a, 2);
            a += __shfl_xor_sync(0xffffffffu, a, 1);
            if (lane == 0) f_s[wid] = 1.0f / (1.0f + __expf(-(a + bfh)));
        }
        __syncthreads();

        // warp 0: 16-lane suffix scan, c_s write, ballot t0
        if (wid == 0) {
            float wrt = (lane < MCH)
                ? router[((size_t)b * Sq + tc + lane) * nm + mid] : 0.f;
            float fv = (lane < MCH) ? f_s[lane] : 1.0f;
            float incl = fv;
            #pragma unroll
            for (int off = 1; off < 32; off <<= 1) {
                float v = __shfl_down_sync(0xffffffffu, incl, off);
                if (lane + off < 32) incl *= v;
            }
            float excl = __shfl_down_sync(0xffffffffu, incl, 1);
            if (lane == 31) excl = 1.0f;
            float sp0 = s_sp;
            float sp = sp0 * excl;               // suffix product after t=tc+lane
            unsigned int m = __ballot_sync(0xffffffffu,
                                           (lane < MCH) && (sp >= CUT));
            if (lane < MCH) c_s[tc + lane] = wrt * sp;
            if (lane == 0) {
                s_newsp = sp0 * incl;
                s_t0i = m ? (__ffs(m) - 1) : 0;
            }
        }
        __syncthreads();

        float nsp = s_newsp;
        if (nsp < CUT) { t0_exact = tc + s_t0i; ci_low = ci; break; }
        if (tid == 0) s_sp = nsp;
        if (ci == 0) { P = nsp; t0_exact = 0; ci_low = 0; }
    }

    // weights resident before phase 2 (also orders c_s / xbig)
    asm volatile("cp.async.wait_group 0;" ::: "memory");
    __syncthreads();

    // ---- phase 2: end-aligned 16-step chunks, f32x2 ----
    int dg = tid >> 4, eg = tid & 15, d0 = dg * 4, e0 = eg * 8;
    u64 acc2[4][4];
    u64 z = pack2(0.f, 0.f);
    #pragma unroll
    for (int r = 0; r < 4; r++)
        #pragma unroll
        for (int q = 0; q < 4; q++) acc2[r][q] = z;

    float* op = half ? v_s : k_s;
    const float* Ws = half ? Wv_s : Wk_s;

    int n = Sq - t0_exact;
    int t_start = Sq - (((n + MCH - 1) >> 4) << 4);
    int lowt = ci_low << 4;
    if (t_start < lowt) t_start = lowt;

    for (int tc = t_start; tc < Sq; tc += MCH) {
        int ci2 = tc >> 4;
        const float* xbase;
        if (ci2 == ci_low || ci2 == ci_low + 1) {
            xbase = &xbig[((ci2 & 1) * 16) * 132];   // resident (common case)
        } else {
            // very rare deep window: restage (ascending order -> clobber-safe)
            __syncthreads();
            int row = tid >> 5, q = tid & 31;
            float4 xv = *(const float4*)&x[((size_t)b * Sq + tc + row) * Dq + q * 4];
            *(float4*)&xbig[((ci2 & 1) * 16 + row) * 132 + q * 4] = xv;
            xbase = &xbig[((ci2 & 1) * 16) * 132];
            __syncthreads();
        }

        // projection: 1 row x 8 cols as 4 packed f32x2 pairs
        u64 pa2[4] = {z, z, z, z};
        #pragma unroll 4
        for (int d4 = 0; d4 < Dq / 4; d4++) {
            float4 xa = *(const float4*)&xbase[rg * 132 + d4 * 4];
            float xr[4] = {xa.x, xa.y, xa.z, xa.w};
            #pragma unroll
            for (int u = 0; u < 4; u++) {
                int d = d4 * 4 + u;
                ulonglong2 wA = *(const ulonglong2*)&Ws[d * Dq + cg * 8];
                ulonglong2 wB = *(const ulonglong2*)&Ws[d * Dq + cg * 8 + 4];
                u64 xb = pack2(xr[u], xr[u]);
                pa2[0] = fma2(xb, wA.x, pa2[0]);
                pa2[1] = fma2(xb, wA.y, pa2[1]);
                pa2[2] = fma2(xb, wB.x, pa2[2]);
                pa2[3] = fma2(xb, wB.y, pa2[3]);
            }
        }
        if (tc != t_start) __syncthreads();   // prior outer reads of k_s/v_s done
        {
            float scale = half ? 1.0f : c_s[tc + rg];   // fold c_t into k rows
            float o[8];
            #pragma unroll
            for (int q = 0; q < 4; q++) unpack2(pa2[q], o[2 * q], o[2 * q + 1]);
            #pragma unroll
            for (int j = 0; j < 8; j++) o[j] = (o[j] + bias[j]) * scale;
            *(float4*)&op[rg * 132 + cg * 8]     = make_float4(o[0], o[1], o[2], o[3]);
            *(float4*)&op[rg * 132 + cg * 8 + 4] = make_float4(o[4], o[5], o[6], o[7]);
        }
        __syncthreads();

        // rank-16 outer-product update: 4x8 tile as 4x4 packed pairs
        #pragma unroll 4
        for (int i = 0; i < MCH; i++) {
            float4 k0 = *(const float4*)&k_s[i * 132 + d0];
            ulonglong2 va = *(const ulonglong2*)&v_s[i * 132 + e0];
            ulonglong2 vb = *(const ulonglong2*)&v_s[i * 132 + e0 + 4];
            u64 kp[4] = {pack2(k0.x, k0.x), pack2(k0.y, k0.y),
                         pack2(k0.z, k0.z), pack2(k0.w, k0.w)};
            #pragma unroll
            for (int r = 0; r < 4; r++) {
                acc2[r][0] = fma2(kp[r], va.x, acc2[r][0]);
                acc2[r][1] = fma2(kp[r], va.y, acc2[r][1]);
                acc2[r][2] = fma2(kp[r], vb.x, acc2[r][2]);
                acc2[r][3] = fma2(kp[r], vb.y, acc2[r][3]);
            }
        }
    }

    // unpack accumulators
    float acc[4][8];
    #pragma unroll
    for (int r = 0; r < 4; r++)
        #pragma unroll
        for (int q = 0; q < 4; q++)
            unpack2(acc2[r][q], acc[r][2 * q], acc[r][2 * q + 1]);

    // add P*M0 only if the full scan completed (else contribution < CUT)
    if (P != 0.0f) {
        #pragma unroll
        for (int r = 0; r < 4; r++) {
            float4 m0 = *(const float4*)&M0[(((size_t)bh * Dq) + d0 + r) * Dq + e0];
            float4 m1 = *(const float4*)&M0[(((size_t)bh * Dq) + d0 + r) * Dq + e0 + 4];
            acc[r][0] += P * m0.x; acc[r][1] += P * m0.y;
            acc[r][2] += P * m0.z; acc[r][3] += P * m0.w;
            acc[r][4] += P * m1.x; acc[r][5] += P * m1.y;
            acc[r][6] += P * m1.z; acc[r][7] += P * m1.w;
        }
    }

    #pragma unroll
    for (int r = 0; r < 4; r++) {
        *(float4*)&out[(((size_t)bh * Dq) + d0 + r) * Dq + e0] =
            make_float4(acc[r][0], acc[r][1], acc[r][2], acc[r][3]);
        *(float4*)&out[(((size_t)bh * Dq) + d0 + r) * Dq + e0 + 4] =
            make_float4(acc[r][4], acc[r][5], acc[r][6], acc[r][7]);
    }
}

// ---------------------------------------------------------------------------
extern "C" void kernel_launch(void* const* d_in, const int* in_sizes, int n_in,
                              void* d_out, int out_size)
{
    const float* x      = (const float*)d_in[0];
    const float* M      = (const float*)d_in[1];
    const float* router = (const float*)d_in[2];
    const int*   memid  = (const int*)d_in[3];
    const float* Wk     = (const float*)d_in[4];
    const float* bk     = (const float*)d_in[5];
    const float* Wv     = (const float*)d_in[6];
    const float* bv     = (const float*)d_in[7];
    const float* Wf     = (const float*)d_in[8];
    const float* bf     = (const float*)d_in[9];

    int nm = in_sizes[2] / (Bq * Sq);   // router last-dim (4)

    static bool attr_done = false;
    if (!attr_done) {
        cudaFuncSetAttribute(fused_kernel,
                             cudaFuncAttributeMaxDynamicSharedMemorySize,
                             SMEM_FLOATS * 4);
        attr_done = true;
    }
    fused_kernel<<<BH, 512, SMEM_FLOATS * 4>>>(
        x, M, router, memid, Wk, bk, Wv, bv, Wf, bf, (float*)d_out, nm);
}

// round 17
// speedup vs baseline: 1.4550x; 1.0073x over previous
#include <cuda_runtime.h>
#include <math.h>

#define Bq 16
#define Sq 2048
#define Dq 128
#define Hq 8
#define BH 128
#define MCH 16
#define NCH (Sq/MCH)           // 128
#define CUT 1e-3f

// dynamic smem float layout
#define OFF_WK 0
#define OFF_WV 16384
#define OFF_XB 32768           // 32 rows * 132 (two 16-row parity buffers)
#define OFF_K  36992           // 16*132
#define OFF_V  39104           // 16*132
#define OFF_C  41216           // 2048
#define OFF_WF 43264           // full Wf slab, 1024 floats
#define OFF_RT 44288           // router slab last chunk, 16*nm floats (<=160)
#define SMEM_FLOATS 44448

typedef unsigned long long u64;

__device__ __forceinline__ u64 pack2(float lo, float hi) {
    u64 r; asm("mov.b64 %0, {%1, %2};" : "=l"(r) : "f"(lo), "f"(hi)); return r;
}
__device__ __forceinline__ void unpack2(u64 v, float& lo, float& hi) {
    asm("mov.b64 {%0, %1}, %2;" : "=f"(lo), "=f"(hi) : "l"(v));
}
__device__ __forceinline__ u64 fma2(u64 a, u64 b, u64 c) {
    u64 d; asm("fma.rn.f32x2 %0, %1, %2, %3;" : "=l"(d) : "l"(a), "l"(b), "l"(c));
    return d;
}
__device__ __forceinline__ void cpa16(float* dst, const float* src) {
    unsigned int ds = (unsigned int)__cvta_generic_to_shared(dst);
    asm volatile("cp.async.ca.shared.global [%0], [%1], 16;" :: "r"(ds), "l"(src));
}

// ---------------------------------------------------------------------------
// One block per (b,h). Warp-specialized single-wait pipeline:
//  prologue: cp.async A = {x last chunk, Wf slab, router slab}, B = Wk_h/Wv_h;
//            wait all; ONE sync.
//  warps 0-15: project chunk 127 (unscaled k/v + bias) -> k_s/v_s.
//  warp 0 FIRST: full backward scan in registers (lane-pair dots, width-16
//            shfl suffix scan, ballot t0) -> c_s, s_t0, s_P; then its slice.
//  sync; outer-product chunk 127 with c folded at read; rare earlier chunks
//  via sequential fallback; acc += P*M0 (P!=0 only if full scan); store.
// ---------------------------------------------------------------------------
__global__ __launch_bounds__(512) void fused_kernel(
    const float* __restrict__ x, const float* __restrict__ M0,
    const float* __restrict__ router, const int* __restrict__ memid,
    const float* __restrict__ Wk, const float* __restrict__ bk,
    const float* __restrict__ Wv, const float* __restrict__ bv,
    const float* __restrict__ Wf, const float* __restrict__ bf,
    float* __restrict__ out, int nm)
{
    extern __shared__ float sm[];
    float* Wk_s  = sm + OFF_WK;
    float* Wv_s  = sm + OFF_WV;
    float* xbig  = sm + OFF_XB;   // [32][132]; buffer = (chunk&1)*16 rows
    float* k_s   = sm + OFF_K;    // [16][132] unscaled
    float* v_s   = sm + OFF_V;
    float* c_s   = sm + OFF_C;    // indexed by global t
    float* wf_all= sm + OFF_WF;   // Wf[d][h'] row-major (d*Hq+h')
    float* rtr_s = sm + OFF_RT;   // router[b, 2032+l, e] = rtr_s[l*nm+e]

    __shared__ int   s_t0, s_ciLow;
    __shared__ float s_P;

    int tid = threadIdx.x, bh = blockIdx.x, b = bh >> 3, h = bh & 7;
    int wid = tid >> 5, lane = tid & 31;

    // ---- prologue: async prefetches ----
    {   // x last chunk -> xbig buf1 (chunk 127 parity = 1)
        int row = tid >> 5, q = tid & 31;
        cpa16(&xbig[(16 + row) * 132 + q * 4],
              &x[((size_t)b * Sq + (Sq - MCH) + row) * Dq + q * 4]);
    }
    if (tid < 256) cpa16(&wf_all[tid * 4], &Wf[tid * 4]);
    if (tid >= 256 && tid < 256 + 4 * nm) {
        int j = tid - 256;
        cpa16(&rtr_s[j * 4], &router[((size_t)b * Sq + (Sq - MCH)) * nm + j * 4]);
    }
    asm volatile("cp.async.commit_group;" ::: "memory");

    for (int idx = tid; idx < Dq * 32; idx += 512) {
        int d = idx >> 5, q = idx & 31;
        cpa16(&Wk_s[d * Dq + q * 4], &Wk[(size_t)d * (Dq * Hq) + h * Dq + q * 4]);
        cpa16(&Wv_s[d * Dq + q * 4], &Wv[(size_t)d * (Dq * Hq) + h * Dq + q * 4]);
    }
    asm volatile("cp.async.commit_group;" ::: "memory");

    float bfh = bf[h];
    int mid = *memid;

    int half = tid >> 8, id2 = tid & 255;
    int rg = id2 & 15, cg = id2 >> 4;
    float bias[8];
    {
        const float* bsrc = half ? bv : bk;
        #pragma unroll
        for (int j = 0; j < 8; j++) bias[j] = bsrc[h * Dq + cg * 8 + j];
    }

    asm volatile("cp.async.wait_group 0;" ::: "memory");
    __syncthreads();                       // everything staged & visible

    // ---- warp 0: full backward scan in registers ----
    if (wid == 0) {
        float sp = 1.0f, Pv = 0.0f;
        int t0r = 0, ciLowR = 0;
        int p = lane >> 1, halfl = lane & 1;

        for (int ci = NCH - 1; ci >= 0; ci--) {
            int tc = ci * MCH, buf = (ci & 1) * 16;
            float rtr;
            if (ci == NCH - 1) {
                rtr = (lane < MCH) ? rtr_s[lane * nm + mid] : 0.f;
            } else {
                // stage this chunk's x (warp 0 alone; rare)
                for (int j = 0; j < MCH; j++) {
                    float4 xv = *(const float4*)&x[((size_t)b * Sq + tc + j) * Dq + lane * 4];
                    *(float4*)&xbig[(buf + j) * 132 + lane * 4] = xv;
                }
                rtr = (lane < MCH)
                    ? router[((size_t)b * Sq + tc + lane) * nm + mid] : 0.f;
            }
            // logit for t = p; lane pair splits d range
            float a = 0.f;
            #pragma unroll 4
            for (int j = 0; j < 16; j++) {
                int d = halfl * 64 + j * 4;
                float4 xv = *(const float4*)&xbig[(buf + p) * 132 + d];
                a += xv.x * wf_all[(d + 0) * Hq + h] + xv.y * wf_all[(d + 1) * Hq + h]
                   + xv.z * wf_all[(d + 2) * Hq + h] + xv.w * wf_all[(d + 3) * Hq + h];
            }
            a += __shfl_xor_sync(0xffffffffu, a, 1);
            float lt = __shfl_sync(0xffffffffu, a, (2 * lane) & 31);
            float fv = (lane < MCH) ? 1.0f / (1.0f + __expf(-(lt + bfh))) : 1.0f;

            // width-16 suffix-product scan
            float incl = fv;
            #pragma unroll
            for (int off = 1; off < 16; off <<= 1) {
                float v = __shfl_down_sync(0xffffffffu, incl, off);
                if (lane + off < 16) incl *= v;
            }
            float excl = __shfl_down_sync(0xffffffffu, incl, 1);
            if (lane == 15) excl = 1.0f;
            float spv = sp * excl;                 // suffix after t=tc+lane
            if (lane < MCH) c_s[tc + lane] = rtr * spv;
            unsigned m = __ballot_sync(0xffffffffu, (lane < MCH) && (spv >= CUT));
            float nsp = sp * __shfl_sync(0xffffffffu, incl, 0);

            if (nsp < CUT) {
                t0r = tc + (m ? (__ffs(m) - 1) : MCH);
                ciLowR = ci;
                break;
            }
            sp = nsp;
            if (ci == 0) { Pv = nsp; t0r = 0; ciLowR = 0; }
        }
        if (lane == 0) { s_t0 = t0r; s_P = Pv; s_ciLow = ciLowR; }
    }

    // ---- projection of chunk 127 (all warps; warp 0 after its scan) ----
    u64 z = pack2(0.f, 0.f);
    float* op = half ? v_s : k_s;
    const float* Ws = half ? Wv_s : Wk_s;
    {
        const float* xbase = &xbig[16 * 132];      // chunk 127 buffer
        u64 pa2[4] = {z, z, z, z};
        #pragma unroll 4
        for (int d4 = 0; d4 < Dq / 4; d4++) {
            float4 xa = *(const float4*)&xbase[rg * 132 + d4 * 4];
            float xr[4] = {xa.x, xa.y, xa.z, xa.w};
            #pragma unroll
            for (int u = 0; u < 4; u++) {
                int d = d4 * 4 + u;
                ulonglong2 wA = *(const ulonglong2*)&Ws[d * Dq + cg * 8];
                ulonglong2 wB = *(const ulonglong2*)&Ws[d * Dq + cg * 8 + 4];
                u64 xb = pack2(xr[u], xr[u]);
                pa2[0] = fma2(xb, wA.x, pa2[0]);
                pa2[1] = fma2(xb, wA.y, pa2[1]);
                pa2[2] = fma2(xb, wB.x, pa2[2]);
                pa2[3] = fma2(xb, wB.y, pa2[3]);
            }
        }
        float o[8];
        #pragma unroll
        for (int q = 0; q < 4; q++) unpack2(pa2[q], o[2 * q], o[2 * q + 1]);
        #pragma unroll
        for (int j = 0; j < 8; j++) o[j] += bias[j];
        *(float4*)&op[rg * 132 + cg * 8]     = make_float4(o[0], o[1], o[2], o[3]);
        *(float4*)&op[rg * 132 + cg * 8 + 4] = make_float4(o[4], o[5], o[6], o[7]);
    }
    __syncthreads();   // k_s/v_s + c_s + s_t0/s_P/s_ciLow all ready

    // ---- outer products (c folded at read) ----
    int dg = tid >> 4, eg = tid & 15, d0 = dg * 4, e0 = eg * 8;
    u64 acc2[4][4];
    #pragma unroll
    for (int r = 0; r < 4; r++)
        #pragma unroll
        for (int q = 0; q < 4; q++) acc2[r][q] = z;

    // chunk 127
    {
        int tcc = Sq - MCH;
        #pragma unroll 4
        for (int i = 0; i < MCH; i++) {
            float cv = c_s[tcc + i];
            float4 k0 = *(const float4*)&k_s[i * 132 + d0];
            ulonglong2 va = *(const ulonglong2*)&v_s[i * 132 + e0];
            ulonglong2 vb = *(const ulonglong2*)&v_s[i * 132 + e0 + 4];
            u64 kp[4] = {pack2(k0.x * cv, k0.x * cv), pack2(k0.y * cv, k0.y * cv),
                         pack2(k0.z * cv, k0.z * cv), pack2(k0.w * cv, k0.w * cv)};
            #pragma unroll
            for (int r = 0; r < 4; r++) {
                acc2[r][0] = fma2(kp[r], va.x, acc2[r][0]);
                acc2[r][1] = fma2(kp[r], va.y, acc2[r][1]);
                acc2[r][2] = fma2(kp[r], vb.x, acc2[r][2]);
                acc2[r][3] = fma2(kp[r], vb.y, acc2[r][3]);
            }
        }
    }

    // rare: earlier chunks in the window
    int t0v = s_t0, ciLow = s_ciLow;
    int n = Sq - t0v;
    int t_start = Sq - ((n + MCH - 1) & ~(MCH - 1));
    int lowt = ciLow * MCH;
    if (t_start < lowt) t_start = lowt;

    for (int tc = t_start; tc < Sq - MCH; tc += MCH) {
        __syncthreads();    // prior outer reads of k_s/v_s complete
        int ci2 = tc >> 4;
        const float* xbase;
        if (ci2 == ciLow || ci2 == ciLow + 1) {
            xbase = &xbig[((ci2 & 1) * 16) * 132];
        } else {
            int row = tid >> 5, q = tid & 31;
            float4 xv = *(const float4*)&x[((size_t)b * Sq + tc + row) * Dq + q * 4];
            *(float4*)&xbig[((ci2 & 1) * 16 + row) * 132 + q * 4] = xv;
            xbase = &xbig[((ci2 & 1) * 16) * 132];
            __syncthreads();
        }

        u64 pa2[4] = {z, z, z, z};
        #pragma unroll 4
        for (int d4 = 0; d4 < Dq / 4; d4++) {
            float4 xa = *(const float4*)&xbase[rg * 132 + d4 * 4];
            float xr[4] = {xa.x, xa.y, xa.z, xa.w};
            #pragma unroll
            for (int u = 0; u < 4; u++) {
                int d = d4 * 4 + u;
                ulonglong2 wA = *(const ulonglong2*)&Ws[d * Dq + cg * 8];
                ulonglong2 wB = *(const ulonglong2*)&Ws[d * Dq + cg * 8 + 4];
                u64 xb = pack2(xr[u], xr[u]);
                pa2[0] = fma2(xb, wA.x, pa2[0]);
                pa2[1] = fma2(xb, wA.y, pa2[1]);
                pa2[2] = fma2(xb, wB.x, pa2[2]);
                pa2[3] = fma2(xb, wB.y, pa2[3]);
            }
        }
        float o[8];
        #pragma unroll
        for (int q = 0; q < 4; q++) unpack2(pa2[q], o[2 * q], o[2 * q + 1]);
        #pragma unroll
        for (int j = 0; j < 8; j++) o[j] += bias[j];
        *(float4*)&op[rg * 132 + cg * 8]     = make_float4(o[0], o[1], o[2], o[3]);
        *(float4*)&op[rg * 132 + cg * 8 + 4] = make_float4(o[4], o[5], o[6], o[7]);
        __syncthreads();

        #pragma unroll 4
        for (int i = 0; i < MCH; i++) {
            float cv = c_s[tc + i];
            float4 k0 = *(const float4*)&k_s[i * 132 + d0];
            ulonglong2 va = *(const ulonglong2*)&v_s[i * 132 + e0];
            ulonglong2 vb = *(const ulonglong2*)&v_s[i * 132 + e0 + 4];
            u64 kp[4] = {pack2(k0.x * cv, k0.x * cv), pack2(k0.y * cv, k0.y * cv),
                         pack2(k0.z * cv, k0.z * cv), pack2(k0.w * cv, k0.w * cv)};
            #pragma unroll
            for (int r = 0; r < 4; r++) {
                acc2[r][0] = fma2(kp[r], va.x, acc2[r][0]);
                acc2[r][1] = fma2(kp[r], va.y, acc2[r][1]);
                acc2[r][2] = fma2(kp[r], vb.x, acc2[r][2]);
                acc2[r][3] = fma2(kp[r], vb.y, acc2[r][3]);
            }
        }
    }

    // unpack
    float acc[4][8];
    #pragma unroll
    for (int r = 0; r < 4; r++)
        #pragma unroll
        for (int q = 0; q < 4; q++)
            unpack2(acc2[r][q], acc[r][2 * q], acc[r][2 * q + 1]);

    // P*M0 (only if full scan survived; else < CUT)
    float P = s_P;
    if (P != 0.0f) {
        #pragma unroll
        for (int r = 0; r < 4; r++) {
            float4 m0 = *(const float4*)&M0[(((size_t)bh * Dq) + d0 + r) * Dq + e0];
            float4 m1 = *(const float4*)&M0[(((size_t)bh * Dq) + d0 + r) * Dq + e0 + 4];
            acc[r][0] += P * m0.x; acc[r][1] += P * m0.y;
            acc[r][2] += P * m0.z; acc[r][3] += P * m0.w;
            acc[r][4] += P * m1.x; acc[r][5] += P * m1.y;
            acc[r][6] += P * m1.z; acc[r][7] += P * m1.w;
        }
    }

    #pragma unroll
    for (int r = 0; r < 4; r++) {
        *(float4*)&out[(((size_t)bh * Dq) + d0 + r) * Dq + e0] =
            make_float4(acc[r][0], acc[r][1], acc[r][2], acc[r][3]);
        *(float4*)&out[(((size_t)bh * Dq) + d0 + r) * Dq + e0 + 4] =
            make_float4(acc[r][4], acc[r][5], acc[r][6], acc[r][7]);
    }
}

// ---------------------------------------------------------------------------
extern "C" void kernel_launch(void* const* d_in, const int* in_sizes, int n_in,
                              void* d_out, int out_size)
{
    const float* x      = (const float*)d_in[0];
    const float* M      = (const float*)d_in[1];
    const float* router = (const float*)d_in[2];
    const int*   memid  = (const int*)d_in[3];
    const float* Wk     = (const float*)d_in[4];
    const float* bk     = (const float*)d_in[5];
    const float* Wv     = (const float*)d_in[6];
    const float* bv     = (const float*)d_in[7];
    const float* Wf     = (const float*)d_in[8];
    const float* bf     = (const float*)d_in[9];

    int nm = in_sizes[2] / (Bq * Sq);   // router last-dim (4)

    static bool attr_done = false;
    if (!attr_done) {
        cudaFuncSetAttribute(fused_kernel,
                             cudaFuncAttributeMaxDynamicSharedMemorySize,
                             SMEM_FLOATS * 4);
        attr_done = true;
    }
    fused_kernel<<<BH, 512, SMEM_FLOATS * 4>>>(
        x, M, router, memid, Wk, bk, Wv, bv, Wf, bf, (float*)d_out, nm);
}